// round 1
// baseline (speedup 1.0000x reference)
#include <cuda_runtime.h>
#include <math.h>

#define BSZ 4096
#define DIM 128
#define KSEL 200

// ---- scratch (no allocations allowed; __device__ globals are the sanctioned path) ----
__device__ float g_S[(size_t)BSZ * BSZ];   // 64 MB similarity matrix (L2-resident)
__device__ float g_perrow[BSZ];
__device__ float g_validf[BSZ];

// ---------------------------------------------------------------------------
// Monotonic float->uint key: larger key <=> larger float (handles negatives).
// ---------------------------------------------------------------------------
__device__ __forceinline__ unsigned fkey(float x) {
    unsigned u = __float_as_uint(x);
    return u ^ ((unsigned)((int)u >> 31) | 0x80000000u);
}
__device__ __forceinline__ float keyToFloat(unsigned k) {
    unsigned u = (k & 0x80000000u) ? (k ^ 0x80000000u) : ~k;
    return __uint_as_float(u);
}

// ---------------------------------------------------------------------------
// Block reductions (256 threads). Result broadcast to all threads.
// Deterministic within a block (fixed order).
// ---------------------------------------------------------------------------
__device__ __forceinline__ float blockReduceSum(float v, float* red) {
    int lane = threadIdx.x & 31, w = threadIdx.x >> 5;
#pragma unroll
    for (int o = 16; o; o >>= 1) v += __shfl_xor_sync(0xFFFFFFFFu, v, o);
    __syncthreads();               // protect red[] reuse across calls
    if (lane == 0) red[w] = v;
    __syncthreads();
    float t = red[0];
#pragma unroll
    for (int x = 1; x < 8; x++) t += red[x];
    return t;
}

__device__ __forceinline__ float blockReduceMax(float v, float* red) {
    int lane = threadIdx.x & 31, w = threadIdx.x >> 5;
#pragma unroll
    for (int o = 16; o; o >>= 1) v = fmaxf(v, __shfl_xor_sync(0xFFFFFFFFu, v, o));
    __syncthreads();
    if (lane == 0) red[w] = v;
    __syncthreads();
    float t = red[0];
#pragma unroll
    for (int x = 1; x < 8; x++) t = fmaxf(t, red[x]);
    return t;
}

// ---------------------------------------------------------------------------
// Symmetric GEMM: S = F * F^T. Only upper-triangular block tiles computed
// (by <= bx); lower triangle written via an smem-staged transpose.
// Tile 64x64, 256 threads, 4x4 per thread, K split into 2 stages of 64.
// Smem A/B tiles stored K-major with an XOR swizzle so both the transpose
// store on load and the float4 reads in the mainloop are bank-conflict-free.
// ---------------------------------------------------------------------------
__global__ __launch_bounds__(256) void gemm_sym(const float* __restrict__ F) {
    int bx = blockIdx.x, by = blockIdx.y;
    if (by > bx) return;                     // symmetric: upper triangle only
    const int bi = by * 64, bj = bx * 64;

    __shared__ float sh[8192];               // As[64k][64m] | Bs[64k][64m]; reused as Ct
    float* As = sh;
    float* Bs = sh + 4096;

    int tid  = threadIdx.x;
    int lane = tid & 31, warp = tid >> 5;
    int r    = lane >> 2;                    // 0..7   row-within-warp
    int kql  = lane & 3;                     // 0..3   float4-within-k
    int rowA = warp * 8 + r;                 // 0..63
    int tx   = tid & 15, ty = tid >> 4;

    float acc[4][4] = {};
    const float4* F4 = reinterpret_cast<const float4*>(F);

#pragma unroll
    for (int stage = 0; stage < 2; stage++) {
        if (stage) __syncthreads();          // previous compute done before overwrite
#pragma unroll
        for (int it = 0; it < 4; it++) {
            int kq = it * 4 + kql;           // 0..15 (local float4 index in k)
            float4 va = F4[(size_t)(bi + rowA) * 32 + stage * 16 + kq];
            float4 vb = F4[(size_t)(bj + rowA) * 32 + stage * 16 + kq];
            int col = rowA ^ (kql << 3);     // XOR swizzle -> conflict-free STS
            int kb  = kq * 4;
            As[(kb + 0) * 64 + col] = va.x; As[(kb + 1) * 64 + col] = va.y;
            As[(kb + 2) * 64 + col] = va.z; As[(kb + 3) * 64 + col] = va.w;
            Bs[(kb + 0) * 64 + col] = vb.x; Bs[(kb + 1) * 64 + col] = vb.y;
            Bs[(kb + 2) * 64 + col] = vb.z; Bs[(kb + 3) * 64 + col] = vb.w;
        }
        __syncthreads();
#pragma unroll 8
        for (int k = 0; k < 64; k++) {
            int X = ((k >> 2) & 3) << 3;     // matches store swizzle
            float4 a = *reinterpret_cast<const float4*>(&As[k * 64 + ((ty * 4) ^ X)]);
            float4 b = *reinterpret_cast<const float4*>(&Bs[k * 64 + ((tx * 4) ^ X)]);
            acc[0][0] += a.x * b.x; acc[0][1] += a.x * b.y; acc[0][2] += a.x * b.z; acc[0][3] += a.x * b.w;
            acc[1][0] += a.y * b.x; acc[1][1] += a.y * b.y; acc[1][2] += a.y * b.z; acc[1][3] += a.y * b.w;
            acc[2][0] += a.z * b.x; acc[2][1] += a.z * b.y; acc[2][2] += a.z * b.z; acc[2][3] += a.z * b.w;
            acc[3][0] += a.w * b.x; acc[3][1] += a.w * b.y; acc[3][2] += a.w * b.z; acc[3][3] += a.w * b.w;
        }
    }

    // direct (upper) tile write, float4 coalesced
#pragma unroll
    for (int rr = 0; rr < 4; rr++) {
        float4 v = make_float4(acc[rr][0], acc[rr][1], acc[rr][2], acc[rr][3]);
        *reinterpret_cast<float4*>(&g_S[(size_t)(bi + ty * 4 + rr) * BSZ + bj + tx * 4]) = v;
    }

    if (bx != by) {                          // mirror tile via smem transpose stage
        __syncthreads();                     // compute reads of As/Bs done
#pragma unroll
        for (int jj = 0; jj < 4; jj++)
#pragma unroll
            for (int rr = 0; rr < 4; rr++)
                sh[(tx * 4 + jj) * 68 + ty * 4 + rr] = acc[rr][jj];  // Ct[col][row], pad 68
        __syncthreads();
        int row2 = tid >> 2, cseg = (tid & 3) * 16;
#pragma unroll
        for (int q = 0; q < 4; q++) {
            float4 v = *reinterpret_cast<const float4*>(&sh[row2 * 68 + cseg + q * 4]);
            *reinterpret_cast<float4*>(&g_S[(size_t)(bj + row2) * BSZ + bi + cseg + q * 4]) = v;
        }
    }
}

// ---------------------------------------------------------------------------
// Per-row pass: one block per anchor row i.
//  - row of S cached in smem (16 KB)
//  - row max, positive-pair sums
//  - exact top-200 negative selection via 4-pass MSB radix-select (256 bins)
//  - denom, per-row loss -> g_perrow / g_validf
// ---------------------------------------------------------------------------
__global__ __launch_bounds__(256) void row_kernel(const int* __restrict__ labels) {
    __shared__ float s[BSZ];                 // 16 KB
    __shared__ unsigned char flg[BSZ];       // 4 KB: 1 = same label as anchor
    __shared__ unsigned int hist[256];
    __shared__ float red[8];
    __shared__ unsigned int bc[2];

    const int i   = blockIdx.x;
    const int tid = threadIdx.x;
    const int myLab = labels[i];

    const float4* S4 = reinterpret_cast<const float4*>(g_S + (size_t)i * BSZ);
    const int4*   L4 = reinterpret_cast<const int4*>(labels);
    for (int q = tid; q < BSZ / 4; q += 256) {
        float4 v = S4[q];
        int4   l = L4[q];
        s[q * 4 + 0] = v.x; s[q * 4 + 1] = v.y; s[q * 4 + 2] = v.z; s[q * 4 + 3] = v.w;
        flg[q * 4 + 0] = (l.x == myLab);
        flg[q * 4 + 1] = (l.y == myLab);
        flg[q * 4 + 2] = (l.z == myLab);
        flg[q * 4 + 3] = (l.w == myLab);
    }
    __syncthreads();

    // row max (includes diagonal, matching reference: mask applied AFTER max)
    float m = -1e30f;
    for (int j = tid; j < BSZ; j += 256) m = fmaxf(m, s[j]);
    m = blockReduceMax(m, red);

    // positives: same label, j != i
    float lsum = 0.0f, esum = 0.0f, cntf = 0.0f;
    for (int j = tid; j < BSZ; j += 256) {
        if (flg[j] && j != i) {
            float lg = (s[j] - m) * 10.0f;
            lsum += lg;
            esum += __expf(lg);
            cntf += 1.0f;
        }
    }
    lsum = blockReduceSum(lsum, red);
    esum = blockReduceSum(esum, red);
    cntf = blockReduceSum(cntf, red);
    int cnt    = (int)cntf;
    int negcnt = BSZ - cnt - 1;

    float nsum = 0.0f, tail = 0.0f;
    if (negcnt <= KSEL) {
        for (int j = tid; j < BSZ; j += 256)
            if (!flg[j]) nsum += __expf((s[j] - m) * 10.0f);
        nsum = blockReduceSum(nsum, red);
    } else {
        // exact radix-select of 200th-largest negative (monotonic uint keys)
        unsigned prefix = 0;
        int krem = KSEL;
#pragma unroll
        for (int byte = 3; byte >= 0; byte--) {
            hist[tid] = 0;
            __syncthreads();
            unsigned himask = (byte == 3) ? 0u : (0xFFFFFFFFu << ((byte + 1) * 8));
            int shift = byte * 8;
            for (int j = tid; j < BSZ; j += 256) {
                if (!flg[j]) {
                    unsigned key = fkey(s[j]);
                    if (((key ^ prefix) & himask) == 0)
                        atomicAdd(&hist[(key >> shift) & 255u], 1u);
                }
            }
            __syncthreads();
            if (tid == 0) {
                unsigned cum = 0;
                int b = 255;
                for (; b > 0; b--) {
                    unsigned c = hist[b];
                    if (cum + c >= (unsigned)krem) break;
                    cum += c;
                }
                bc[0] = (unsigned)b;
                bc[1] = cum;
            }
            __syncthreads();
            prefix |= bc[0] << shift;
            krem   -= (int)bc[1];
            __syncthreads();                 // bc/hist safe to reuse next pass
        }
        unsigned Tkey = prefix;              // exact key of the 200th largest
        for (int j = tid; j < BSZ; j += 256) {
            if (!flg[j]) {
                if (fkey(s[j]) > Tkey) nsum += __expf((s[j] - m) * 10.0f);
            }
        }
        nsum = blockReduceSum(nsum, red);
        // krem elements with value exactly == T are included (tie-exact)
        tail = (float)krem * __expf((keyToFloat(Tkey) - m) * 10.0f);
    }

    if (tid == 0) {
        float denom = esum + nsum + tail;
        bool valid  = (myLab > 0) && (cnt > 0);
        g_perrow[i] = valid ? (-2.0f * (lsum / cntf - logf(denom))) : 0.0f;
        g_validf[i] = valid ? 1.0f : 0.0f;
    }
}

// ---------------------------------------------------------------------------
// Deterministic final reduction (fixed order; no float atomics).
// ---------------------------------------------------------------------------
__global__ void finalize(float* __restrict__ out) {
    __shared__ float sp[256], sv[256];
    int tid = threadIdx.x;
    float ps = 0.0f, vs = 0.0f;
    for (int j = tid; j < BSZ; j += 256) {
        ps += g_perrow[j];
        vs += g_validf[j];
    }
    sp[tid] = ps; sv[tid] = vs;
    __syncthreads();
#pragma unroll
    for (int o = 128; o; o >>= 1) {
        if (tid < o) { sp[tid] += sp[tid + o]; sv[tid] += sv[tid + o]; }
        __syncthreads();
    }
    if (tid == 0) out[0] = sp[0] / sv[0];
}

// ---------------------------------------------------------------------------
extern "C" void kernel_launch(void* const* d_in, const int* in_sizes, int n_in,
                              void* d_out, int out_size) {
    (void)in_sizes; (void)n_in; (void)out_size;
    const float* F      = (const float*)d_in[0];
    const int*   labels = (const int*)d_in[1];
    float*       out    = (float*)d_out;

    gemm_sym<<<dim3(64, 64), 256>>>(F);
    row_kernel<<<BSZ, 256>>>(labels);
    finalize<<<1, 256>>>(out);
}

// round 2
// speedup vs baseline: 1.1113x; 1.1113x over previous
#include <cuda_runtime.h>
#include <math.h>

#define BSZ 4096
#define DIM 128
#define KSEL 200

// ---- scratch (no allocations allowed; __device__ globals are the sanctioned path) ----
__device__ float g_S[(size_t)BSZ * BSZ];   // 64 MB similarity matrix
__device__ float g_perrow[BSZ];
__device__ float g_validf[BSZ];

// ---------------------------------------------------------------------------
// packed fp32x2 helpers (Blackwell FFMA2 path — only reachable via PTX)
// ---------------------------------------------------------------------------
__device__ __forceinline__ void fma2(unsigned long long& d,
                                     unsigned long long a,
                                     unsigned long long b) {
    asm("fma.rn.f32x2 %0, %1, %2, %0;" : "+l"(d) : "l"(a), "l"(b));
}
__device__ __forceinline__ unsigned long long splat2(float x) {
    unsigned long long r;
    asm("mov.b64 %0, {%1, %1};" : "=l"(r) : "f"(x));
    return r;
}

// ---------------------------------------------------------------------------
// Block reductions (256 threads). Deterministic fixed order.
// ---------------------------------------------------------------------------
__device__ __forceinline__ float blockReduceSum(float v, float* red) {
    int lane = threadIdx.x & 31, w = threadIdx.x >> 5;
#pragma unroll
    for (int o = 16; o; o >>= 1) v += __shfl_xor_sync(0xFFFFFFFFu, v, o);
    __syncthreads();
    if (lane == 0) red[w] = v;
    __syncthreads();
    float t = red[0];
#pragma unroll
    for (int x = 1; x < 8; x++) t += red[x];
    return t;
}
__device__ __forceinline__ float blockReduceMax(float v, float* red) {
    int lane = threadIdx.x & 31, w = threadIdx.x >> 5;
#pragma unroll
    for (int o = 16; o; o >>= 1) v = fmaxf(v, __shfl_xor_sync(0xFFFFFFFFu, v, o));
    __syncthreads();
    if (lane == 0) red[w] = v;
    __syncthreads();
    float t = red[0];
#pragma unroll
    for (int x = 1; x < 8; x++) t = fmaxf(t, red[x]);
    return t;
}

// ---------------------------------------------------------------------------
// Symmetric GEMM: S = F * F^T.  128x128 tiles, 256 threads, 8x8 per thread,
// packed f32x2 accumulation. Triangular 1D grid (528 tiles), mirror written
// via chunked smem transpose. K processed in 8 chunks of 16.
// ---------------------------------------------------------------------------
__global__ __launch_bounds__(256, 2) void gemm_sym(const float* __restrict__ F) {
    // decode triangular tile index -> (by, bx), bx >= by
    int lin = blockIdx.x;
    int by = 0;
    while (lin >= 32 - by) { lin -= 32 - by; by++; }
    int bx = by + lin;
    const int bi = by * 128, bj = bx * 128;

    __shared__ float sh[4224];               // As[16][132] | Bs[16][132]; reused as St[32][132]
    float* As = sh;
    float* Bs = sh + 2112;

    const int tid = threadIdx.x;
    const int tx = tid & 15, ty = tid >> 4;  // 16x16 thread grid

    // accumulators: 4 row-pairs x 8 cols, packed (row, row+1) in f32x2
    unsigned long long acc2[4][8];
#pragma unroll
    for (int p = 0; p < 4; p++)
#pragma unroll
        for (int c = 0; c < 8; c++) acc2[p][c] = 0ULL;

    const float4* F4 = reinterpret_cast<const float4*>(F);
    const int kq = tid & 3;                  // float4 slot within 16-k chunk
    const int lm = tid >> 2;                 // 0..63

#pragma unroll 1
    for (int chunk = 0; chunk < 8; chunk++) {
        if (chunk) __syncthreads();
        // load A,B chunk: rows lm and lm+64, k = chunk*16 + kq*4 + c
        float4 va0 = F4[(size_t)(bi + lm) * 32 + chunk * 4 + kq];
        float4 va1 = F4[(size_t)(bi + lm + 64) * 32 + chunk * 4 + kq];
        float4 vb0 = F4[(size_t)(bj + lm) * 32 + chunk * 4 + kq];
        float4 vb1 = F4[(size_t)(bj + lm + 64) * 32 + chunk * 4 + kq];
        {
            int kb = kq * 4;
            As[(kb + 0) * 132 + lm] = va0.x; As[(kb + 1) * 132 + lm] = va0.y;
            As[(kb + 2) * 132 + lm] = va0.z; As[(kb + 3) * 132 + lm] = va0.w;
            As[(kb + 0) * 132 + lm + 64] = va1.x; As[(kb + 1) * 132 + lm + 64] = va1.y;
            As[(kb + 2) * 132 + lm + 64] = va1.z; As[(kb + 3) * 132 + lm + 64] = va1.w;
            Bs[(kb + 0) * 132 + lm] = vb0.x; Bs[(kb + 1) * 132 + lm] = vb0.y;
            Bs[(kb + 2) * 132 + lm] = vb0.z; Bs[(kb + 3) * 132 + lm] = vb0.w;
            Bs[(kb + 0) * 132 + lm + 64] = vb1.x; Bs[(kb + 1) * 132 + lm + 64] = vb1.y;
            Bs[(kb + 2) * 132 + lm + 64] = vb1.z; Bs[(kb + 3) * 132 + lm + 64] = vb1.w;
        }
        __syncthreads();

        const float4* As4 = reinterpret_cast<const float4*>(As);
        const float4* Bs4 = reinterpret_cast<const float4*>(Bs);
#pragma unroll
        for (int k = 0; k < 16; k++) {
            float4 av0 = As4[k * 33 + ty];        // rows ty*4 .. +3
            float4 av1 = As4[k * 33 + 16 + ty];   // rows 64+ty*4 .. +3
            float4 bv0 = Bs4[k * 33 + tx];        // cols tx*4 .. +3
            float4 bv1 = Bs4[k * 33 + 16 + tx];   // cols 64+tx*4 .. +3
            unsigned long long A0 = reinterpret_cast<const ulonglong2*>(&av0)->x;
            unsigned long long A1 = reinterpret_cast<const ulonglong2*>(&av0)->y;
            unsigned long long A2 = reinterpret_cast<const ulonglong2*>(&av1)->x;
            unsigned long long A3 = reinterpret_cast<const ulonglong2*>(&av1)->y;
            unsigned long long B[8];
            B[0] = splat2(bv0.x); B[1] = splat2(bv0.y);
            B[2] = splat2(bv0.z); B[3] = splat2(bv0.w);
            B[4] = splat2(bv1.x); B[5] = splat2(bv1.y);
            B[6] = splat2(bv1.z); B[7] = splat2(bv1.w);
#pragma unroll
            for (int c = 0; c < 8; c++) {
                fma2(acc2[0][c], A0, B[c]);
                fma2(acc2[1][c], A1, B[c]);
                fma2(acc2[2][c], A2, B[c]);
                fma2(acc2[3][c], A3, B[c]);
            }
        }
    }

    // lane view of accumulators
    auto accf = [&](int p, int c, int half) -> float {
        float2 f = *reinterpret_cast<float2*>(&acc2[p][c]);
        return half ? f.y : f.x;
    };
    // row of pair p, half h:  p<2 -> ty*4 + 2p + h ; p>=2 -> 64 + ty*4 + 2(p-2) + h
    auto rowOf = [&](int p, int h) -> int {
        return (p < 2) ? (ty * 4 + 2 * p + h) : (64 + ty * 4 + 2 * (p - 2) + h);
    };

    // direct (upper-triangle position) tile write, coalesced float4
#pragma unroll
    for (int p = 0; p < 4; p++)
#pragma unroll
        for (int h = 0; h < 2; h++) {
            int r = rowOf(p, h);
            float4 w0 = make_float4(accf(p, 0, h), accf(p, 1, h), accf(p, 2, h), accf(p, 3, h));
            float4 w1 = make_float4(accf(p, 4, h), accf(p, 5, h), accf(p, 6, h), accf(p, 7, h));
            *reinterpret_cast<float4*>(&g_S[(size_t)(bi + r) * BSZ + bj + tx * 4]) = w0;
            *reinterpret_cast<float4*>(&g_S[(size_t)(bi + r) * BSZ + bj + 64 + tx * 4]) = w1;
        }

    if (bx != by) {
        // mirror tile via 4 chunked smem transposes (32 cols each)
#pragma unroll 1
        for (int q = 0; q < 4; q++) {
            __syncthreads();                 // sh free (compute/prev chunk done)
            int cbase = (q < 2) ? (tx * 4 - 32 * q) : (64 + tx * 4 - 32 * q);
            if (cbase >= 0 && cbase < 32) {
                int coff = (q < 2) ? 0 : 4;  // which acc column half
#pragma unroll
                for (int j = 0; j < 4; j++)
#pragma unroll
                    for (int p = 0; p < 4; p++) {
                        sh[(cbase + j) * 132 + rowOf(p, 0)] = accf(p, coff + j, 0);
                        sh[(cbase + j) * 132 + rowOf(p, 1)] = accf(p, coff + j, 1);
                    }
            }
            __syncthreads();
            int cl = tid >> 3, f = tid & 7;  // 32 transposed rows x 128 floats
#pragma unroll
            for (int kk = 0; kk < 4; kk++) {
                int f4 = f + kk * 8;
                float4 v = *reinterpret_cast<const float4*>(&sh[cl * 132 + f4 * 4]);
                *reinterpret_cast<float4*>(
                    &g_S[(size_t)(bj + q * 32 + cl) * BSZ + bi + f4 * 4]) = v;
            }
        }
    }
}

// ---------------------------------------------------------------------------
// Per-row pass: one block per anchor row. Row lives in REGISTERS (16/thread).
// Exact top-200 threshold via 9-ary bisection counting (no histograms, no
// atomics) + exact tie-aware rank over a tiny candidate set.
// ---------------------------------------------------------------------------
__global__ __launch_bounds__(256) void row_kernel(const int* __restrict__ labels) {
    __shared__ float red[8];
    __shared__ unsigned scnt[8][8];          // [warp][threshold]
    __shared__ unsigned scounts[8];
    __shared__ float cand[1024];
    __shared__ unsigned ccount;
    __shared__ float sT;
    __shared__ unsigned sgt;

    const int i   = blockIdx.x;
    const int tid = threadIdx.x;
    const int lane = tid & 31, warp = tid >> 5;
    const int myLab = labels[i];

    const float4* S4 = reinterpret_cast<const float4*>(g_S + (size_t)i * BSZ);
    const int4*   L4 = reinterpret_cast<const int4*>(labels);

    float v[16];
    unsigned negm = 0;                       // bit e: label differs (=> negative, self excluded)
    float m = -1e30f;
#pragma unroll
    for (int q = 0; q < 4; q++) {
        int idx = tid + q * 256;             // float4 index; elems j = idx*4 + c
        float4 x = S4[idx];
        int4   l = L4[idx];
        v[q * 4 + 0] = x.x; v[q * 4 + 1] = x.y; v[q * 4 + 2] = x.z; v[q * 4 + 3] = x.w;
        if (l.x != myLab) negm |= 1u << (q * 4 + 0);
        if (l.y != myLab) negm |= 1u << (q * 4 + 1);
        if (l.z != myLab) negm |= 1u << (q * 4 + 2);
        if (l.w != myLab) negm |= 1u << (q * 4 + 3);
        m = fmaxf(m, fmaxf(fmaxf(x.x, x.y), fmaxf(x.z, x.w)));
    }
    m = blockReduceMax(m, red);              // max over full row incl. diagonal (matches ref)

    // positives: same label, j != i
    float lsum = 0.0f, esum = 0.0f, cntf = 0.0f;
#pragma unroll
    for (int e = 0; e < 16; e++) {
        int j = (tid + (e >> 2) * 256) * 4 + (e & 3);
        if (!((negm >> e) & 1u) && j != i) {
            float lg = (v[e] - m) * 10.0f;
            lsum += lg;
            esum += __expf(lg);
            cntf += 1.0f;
        }
    }
    lsum = blockReduceSum(lsum, red);
    esum = blockReduceSum(esum, red);
    cntf = blockReduceSum(cntf, red);
    const int cnt    = (int)cntf;
    const int negcnt = BSZ - cnt - 1;

    float nsum = 0.0f, tail = 0.0f;
    if (negcnt <= KSEL) {
#pragma unroll
        for (int e = 0; e < 16; e++)
            if ((negm >> e) & 1u) nsum += __expf((v[e] - m) * 10.0f);
        nsum = blockReduceSum(nsum, red);
    } else {
        // --- 9-ary bisection: find bracket (lo, hi] containing the 200th-largest negative
        float lo = -1.01f, hi = 1.01f;
        int cntHi = 0, cntLo = negcnt;       // cnt(> hi), cnt(> lo)
        for (int round = 0; round < 8 && (cntLo - cntHi) > 48; round++) {
            float w = (hi - lo) * (1.0f / 9.0f);
            float t0 = lo + w, t1 = lo + 2*w, t2 = lo + 3*w, t3 = lo + 4*w;
            float t4 = lo + 5*w, t5 = lo + 6*w, t6 = lo + 7*w, t7 = lo + 8*w;
            unsigned c0=0,c1=0,c2=0,c3=0,c4=0,c5=0,c6=0,c7=0;
#pragma unroll
            for (int e = 0; e < 16; e++) {
                if ((negm >> e) & 1u) {
                    float x = v[e];
                    c0 += (x > t0); c1 += (x > t1); c2 += (x > t2); c3 += (x > t3);
                    c4 += (x > t4); c5 += (x > t5); c6 += (x > t6); c7 += (x > t7);
                }
            }
            c0 = __reduce_add_sync(0xFFFFFFFFu, c0);
            c1 = __reduce_add_sync(0xFFFFFFFFu, c1);
            c2 = __reduce_add_sync(0xFFFFFFFFu, c2);
            c3 = __reduce_add_sync(0xFFFFFFFFu, c3);
            c4 = __reduce_add_sync(0xFFFFFFFFu, c4);
            c5 = __reduce_add_sync(0xFFFFFFFFu, c5);
            c6 = __reduce_add_sync(0xFFFFFFFFu, c6);
            c7 = __reduce_add_sync(0xFFFFFFFFu, c7);
            if (lane == 0) {
                scnt[warp][0]=c0; scnt[warp][1]=c1; scnt[warp][2]=c2; scnt[warp][3]=c3;
                scnt[warp][4]=c4; scnt[warp][5]=c5; scnt[warp][6]=c6; scnt[warp][7]=c7;
            }
            __syncthreads();
            if (tid < 8) {
                unsigned s = 0;
#pragma unroll
                for (int wq = 0; wq < 8; wq++) s += scnt[wq][tid];
                scounts[tid] = s;
            }
            __syncthreads();
            // all threads update bracket identically
            float tj[8] = {t0,t1,t2,t3,t4,t5,t6,t7};
            int jstar = 8;
#pragma unroll
            for (int j = 7; j >= 0; j--)
                if ((int)scounts[j] < KSEL) jstar = j;
            if (jstar == 8) {                    // all counts >= K
                lo = tj[7]; cntLo = (int)scounts[7];
            } else if (jstar == 0) {
                hi = tj[0]; cntHi = (int)scounts[0];
            } else {
                lo = tj[jstar - 1]; cntLo = (int)scounts[jstar - 1];
                hi = tj[jstar];     cntHi = (int)scounts[jstar];
            }
            __syncthreads();                     // scounts reads done before next round writes
        }

        // --- gather candidates in (lo, hi]
        if (tid == 0) ccount = 0;
        __syncthreads();
#pragma unroll
        for (int e = 0; e < 16; e++) {
            if ((negm >> e) & 1u) {
                float x = v[e];
                if (x > lo && x <= hi) {
                    unsigned u = atomicAdd(&ccount, 1u);
                    if (u < 1024) cand[u] = x;
                }
            }
        }
        __syncthreads();
        int c = (int)min(ccount, 1024u);

        // --- exact tie-aware rank: find T = 200th-largest negative
        for (int t = tid; t < c; t += 256) {
            float x = cand[t];
            int gt = 0, eq = 0;
            for (int u = 0; u < c; u++) {
                float y = cand[u];
                gt += (y > x);
                eq += (y == x);
            }
            if (cntHi + gt < KSEL && KSEL <= cntHi + gt + eq) {
                sT = x;
                sgt = (unsigned)(cntHi + gt);
            }
        }
        __syncthreads();
        float T = sT;
        int ties = KSEL - (int)sgt;              // how many values == T are included
#pragma unroll
        for (int e = 0; e < 16; e++)
            if (((negm >> e) & 1u) && v[e] > T) nsum += __expf((v[e] - m) * 10.0f);
        nsum = blockReduceSum(nsum, red);
        tail = (float)ties * __expf((T - m) * 10.0f);
    }

    if (tid == 0) {
        float denom = esum + nsum + tail;
        bool valid  = (myLab > 0) && (cnt > 0);
        g_perrow[i] = valid ? (-2.0f * (lsum / cntf - logf(denom))) : 0.0f;
        g_validf[i] = valid ? 1.0f : 0.0f;
    }
}

// ---------------------------------------------------------------------------
// Deterministic final reduction.
// ---------------------------------------------------------------------------
__global__ void finalize(float* __restrict__ out) {
    __shared__ float sp[256], sv[256];
    int tid = threadIdx.x;
    float ps = 0.0f, vs = 0.0f;
    for (int j = tid; j < BSZ; j += 256) {
        ps += g_perrow[j];
        vs += g_validf[j];
    }
    sp[tid] = ps; sv[tid] = vs;
    __syncthreads();
#pragma unroll
    for (int o = 128; o; o >>= 1) {
        if (tid < o) { sp[tid] += sp[tid + o]; sv[tid] += sv[tid + o]; }
        __syncthreads();
    }
    if (tid == 0) out[0] = sp[0] / sv[0];
}

// ---------------------------------------------------------------------------
extern "C" void kernel_launch(void* const* d_in, const int* in_sizes, int n_in,
                              void* d_out, int out_size) {
    (void)in_sizes; (void)n_in; (void)out_size;
    const float* F      = (const float*)d_in[0];
    const int*   labels = (const int*)d_in[1];
    float*       out    = (float*)d_out;

    gemm_sym<<<528, 256>>>(F);
    row_kernel<<<BSZ, 256>>>(labels);
    finalize<<<1, 256>>>(out);
}